// round 13
// baseline (speedup 1.0000x reference)
#include <cuda_runtime.h>
#include <math.h>

// EntropyLoss: x [R=65536, C=1024] f32 row-major.
//   n_j  = max( sqrt(sum_i x_ij^2), 1e-12 )
//   out  = -(1/R) * sum_j (1/n_j) * [ sum_i x*ln(x) - ln(n_j) * sum_i x ]
// (eps=1e-8 inside the reference log contributes <1e-6 relative error; dropped)
//
// R13: the last untested structural lever — the ADDRESS PATTERN. All prior
// rounds (71-75% DRAM regardless of occupancy/MLP/TMA/cache policy) used
// grid-strided rows. This round: block-contiguous partitioning. CTA b owns
// ~88 consecutive FULL rows (~360KB sequential); thread t owns columns
// 4t..4t+3; each unroll-8 batch is a 32KB sequential block. No intra-CTA
// column overlap -> direct atomics into 8 scratch replicas (CTA uses b&7,
// <=93 serialized ops/address). Last CTA folds replicas -> scalar and
// re-zeros all scratch for graph replay.

#define COLS 1024
#define NCTAS 740           // 5 CTAs/SM, one wave
#define NREP 8
#define LN2 0.6931471805599453f

__device__ float g_part[NREP][3][COLS]; // [0]=sum x^2, [1]=sum x, [2]=sum x*log2(x)
__device__ unsigned int g_count;

__global__ __launch_bounds__(256, 5) void el_fused_kernel(const float* __restrict__ x,
                                                          float* __restrict__ out,
                                                          int rows) {
    const int tid = threadIdx.x;
    const int b   = blockIdx.x;

    // block-contiguous row partition: first `rem` CTAs get base+1 rows
    const int base  = rows / NCTAS;            // 88
    const int rem   = rows % NCTAS;            // 416
    const int start = b * base + (b < rem ? b : rem);
    const int cnt   = base + (b < rem ? 1 : 0);

    const float4* __restrict__ p = (const float4*)x;
    const float4* __restrict__ q = p + (long)start * (COLS / 4) + tid;

    float s2[4] = {0.f, 0.f, 0.f, 0.f};
    float s1[4] = {0.f, 0.f, 0.f, 0.f};
    float sx[4] = {0.f, 0.f, 0.f, 0.f};

    const int it8 = cnt & ~7;
    for (int r = 0; r < it8; r += 8) {
        // 8 independent loads, 1KB apart -> one 32KB sequential block per CTA
        // batch. Fixed trip count so ptxas fully unrolls and front-batches.
        #pragma unroll
        for (int u = 0; u < 8; u++) {
            float4 v = q[(long)u * (COLS / 4)];
            float vv[4] = {v.x, v.y, v.z, v.w};
            #pragma unroll
            for (int k = 0; k < 4; k++) {
                float a = vv[k];
                s2[k] = fmaf(a, a, s2[k]);
                s1[k] += a;
                // x*log2(x): at a==0 this is fmaf(0, lg2(1e-37), s) == s
                float l = __log2f(fmaxf(a, 1e-37f));
                sx[k] = fmaf(a, l, sx[k]);
            }
        }
        q += 8 * (COLS / 4);
    }
    for (int r = it8; r < cnt; r++) {
        float4 v = *q;
        q += (COLS / 4);
        float vv[4] = {v.x, v.y, v.z, v.w};
        #pragma unroll
        for (int k = 0; k < 4; k++) {
            float a = vv[k];
            s2[k] = fmaf(a, a, s2[k]);
            s1[k] += a;
            float l = __log2f(fmaxf(a, 1e-37f));
            sx[k] = fmaf(a, l, sx[k]);
        }
    }

    // every thread owns distinct columns -> direct atomics, replicated 8x
    {
        const int rep = b & (NREP - 1);
        #pragma unroll
        for (int k = 0; k < 4; k++) {
            atomicAdd(&g_part[rep][0][4 * tid + k], s2[k]);
            atomicAdd(&g_part[rep][1][4 * tid + k], s1[k]);
            atomicAdd(&g_part[rep][2][4 * tid + k], sx[k]);
        }
    }

    // ---- last CTA does the final combine ----
    __shared__ int amLast;
    __threadfence();
    __syncthreads();
    if (tid == 0) {
        unsigned v = atomicAdd(&g_count, 1u);
        amLast = (v == NCTAS - 1);
    }
    __syncthreads();
    if (!amLast) return;

    float acc = 0.f;
    #pragma unroll
    for (int m = 0; m < 4; m++) {
        const int j = tid + m * 256;
        float S2 = 0.f, S1 = 0.f, SX = 0.f;
        #pragma unroll
        for (int r = 0; r < NREP; r++) {
            S2 += __ldcg(&g_part[r][0][j]);
            S1 += __ldcg(&g_part[r][1][j]);
            SX += __ldcg(&g_part[r][2][j]);
        }
        float n = fmaxf(sqrtf(S2), 1e-12f);
        acc += (SX * LN2 - S1 * logf(n)) / n;
    }
    __syncthreads();   // all reads of g_part done before re-zero

    // re-zero all scratch for the next graph replay
    for (int i = tid; i < NREP * 3 * COLS; i += 256) ((float*)g_part)[i] = 0.0f;
    if (tid == 0) g_count = 0u;

    __shared__ float sm[256];
    sm[tid] = acc;
    __syncthreads();
    #pragma unroll
    for (int s = 128; s > 0; s >>= 1) {
        if (tid < s) sm[tid] += sm[tid + s];
        __syncthreads();
    }
    if (tid == 0) out[0] = -sm[0] / (float)rows;
}

extern "C" void kernel_launch(void* const* d_in, const int* in_sizes, int n_in,
                              void* d_out, int out_size) {
    const float* x = (const float*)d_in[0];
    int rows = in_sizes[0] / COLS;   // 65536
    el_fused_kernel<<<NCTAS, 256>>>(x, (float*)d_out, rows);
}